// round 15
// baseline (speedup 1.0000x reference)
#include <cuda_runtime.h>
#include <cstdint>

#define N_B 8
#define T_S 1024
#define D_IN 512
#define U_D 512
#define H_N 8
#define D_H 64

// Scratch: projected Q/K/V (tf32-rounded; Q pre-scaled) + tf32-rounded W.
__device__ float g_Q[N_B * T_S * U_D];
__device__ float g_K[N_B * T_S * U_D];
__device__ float g_V[N_B * T_S * U_D];
__device__ float g_W[3 * D_IN * U_D];      // tf32(Wq|Wk|Wv), k-major

// ---------------------------------------------------------------------------
// Helpers
// ---------------------------------------------------------------------------
__device__ __forceinline__ uint32_t f2tf32(float x) {
    uint32_t r;
    asm("cvt.rna.tf32.f32 %0, %1;" : "=r"(r) : "f"(x));
    return r;
}
__device__ __forceinline__ float f2tf32f(float x) { return __uint_as_float(f2tf32(x)); }

// D += A*B, m16n8k8 tf32. a[4], b[2] are tf32 bit patterns.
__device__ __forceinline__ void mma_tf32(float* d, const uint32_t* a, const uint32_t* b) {
    asm volatile(
        "mma.sync.aligned.m16n8k8.row.col.f32.tf32.tf32.f32 "
        "{%0,%1,%2,%3},{%4,%5,%6,%7},{%8,%9},{%0,%1,%2,%3};\n"
        : "+f"(d[0]), "+f"(d[1]), "+f"(d[2]), "+f"(d[3])
        : "r"(a[0]), "r"(a[1]), "r"(a[2]), "r"(a[3]), "r"(b[0]), "r"(b[1]));
}

__device__ __forceinline__ void ldsm4(uint32_t& r0, uint32_t& r1, uint32_t& r2, uint32_t& r3,
                                      uint32_t addr) {
    asm volatile("ldmatrix.sync.aligned.m8n8.x4.shared.b16 {%0,%1,%2,%3}, [%4];"
                 : "=r"(r0), "=r"(r1), "=r"(r2), "=r"(r3)
                 : "r"(addr));
}

__device__ __forceinline__ void cp_async16(float* s, const float* g) {
    uint32_t sa = (uint32_t)__cvta_generic_to_shared(s);
    asm volatile("cp.async.cg.shared.global [%0], [%1], 16;\n" :: "r"(sa), "l"(g));
}
__device__ __forceinline__ void cp_commit() { asm volatile("cp.async.commit_group;\n"); }
template <int N>
__device__ __forceinline__ void cp_wait() { asm volatile("cp.async.wait_group %0;\n" :: "n"(N)); }

// ---------------------------------------------------------------------------
// Pre-round W (k-major) - 2 independent float4 per thread (MLP=2).
// ---------------------------------------------------------------------------
__global__ void __launch_bounds__(256) preround_w(
    const float* __restrict__ wq, const float* __restrict__ wk,
    const float* __restrict__ wv) {
    const int NW4 = D_IN * U_D / 4;                // 65536
    const int z = blockIdx.y;
    const float* src = (z == 0) ? wq : (z == 1) ? wk : wv;
    float4* dst = (float4*)g_W + (size_t)z * NW4;
    const int i0 = blockIdx.x * 512 + threadIdx.x;  // two chunks, 256 apart
    float4 a = ((const float4*)src)[i0];
    float4 b = ((const float4*)src)[i0 + 256];
    a.x = f2tf32f(a.x); a.y = f2tf32f(a.y); a.z = f2tf32f(a.z); a.w = f2tf32f(a.w);
    b.x = f2tf32f(b.x); b.y = f2tf32f(b.y); b.z = f2tf32f(b.z); b.w = f2tf32f(b.w);
    dst[i0] = a;
    dst[i0 + 256] = b;
}

// ---------------------------------------------------------------------------
// Projection GEMM (R11 winner, byte-identical pipeline order):
// C[8192,512] = X[8192,512] @ W[512,512]
// B (pre-rounded W, k-major) via cp.async double-buffer, scalar conflict-free
// B-frags (B_LD=136 -> 8*tg+g banks); A (raw X) via register prefetch +
// cvt-at-STS into double buffer. BM=128, BN=128, BK=32; 256 threads;
// warp tile 32x64 (ldsm A). Epilogue rounds output to tf32 (Q folded w/scale).
// ---------------------------------------------------------------------------
#define GBM 128
#define GBN 128
#define GBK 32
#define A_LD 36
#define B_LD 136
#define SM_GEMM ((2 * GBM * A_LD + 2 * GBK * B_LD) * 4)

__global__ void __launch_bounds__(256, 2) proj_gemm(
    const float* __restrict__ Xq, const float* __restrict__ Xk) {
    const float* X;
    const float* W;
    float* C;
    float oscale;
    if (blockIdx.z == 0) { X = Xq; W = g_W; C = g_Q; oscale = 0.04419417382415922f; }
    else if (blockIdx.z == 1) { X = Xk; W = g_W + D_IN * U_D; C = g_K; oscale = 1.0f; }
    else { X = Xk; W = g_W + 2 * D_IN * U_D; C = g_V; oscale = 1.0f; }

    extern __shared__ float sm[];
    float* As = sm;                            // [2][GBM][A_LD]
    float* Bs = sm + 2 * GBM * A_LD;           // [2][GBK][B_LD]

    const int tid = threadIdx.x;
    const int m0 = blockIdx.x * GBM, n0 = blockIdx.y * GBN;
    const int ar = tid >> 3, ac = (tid & 7) * 4;     // A: 32 rows/step, 8 f4/row
    const int br = tid >> 5, bc = (tid & 31) * 4;    // B: 8 rows/step, 32 f4/row

    const int lane = tid & 31, wid = tid >> 5;
    const int g = lane >> 2, tg = lane & 3;
    const int wm = (wid & 3) * 32, wn = (wid >> 2) * 64;

    // ldmatrix A-frag per-lane offset (16x8 pattern, floats)
    const int li = lane & 7, lj = lane >> 3;
    const int aoff = (li + (lj & 1) * 8) * A_LD + (lj >> 1) * 4;
    const uint32_t sA = (uint32_t)__cvta_generic_to_shared(As);

    float acc[2][8][4];
#pragma unroll
    for (int mf = 0; mf < 2; mf++)
#pragma unroll
        for (int nf = 0; nf < 8; nf++)
#pragma unroll
            for (int i = 0; i < 4; i++) acc[mf][nf][i] = 0.f;

    const int NK = D_IN / GBK;  // 16

    float4 pa[4];
    auto ldregA = [&](int kt) {
#pragma unroll
        for (int i = 0; i < 4; i++)
            pa[i] = *(const float4*)(X + (size_t)(m0 + ar + i * 32) * D_IN + kt * GBK + ac);
    };
    auto stsA = [&](int buf) {
#pragma unroll
        for (int i = 0; i < 4; i++) {
            float4 o;
            o.x = f2tf32f(pa[i].x); o.y = f2tf32f(pa[i].y);
            o.z = f2tf32f(pa[i].z); o.w = f2tf32f(pa[i].w);
            *(float4*)(As + buf * GBM * A_LD + (ar + i * 32) * A_LD + ac) = o;
        }
    };
    auto issueB = [&](int buf, int kt) {
        const float* b_src = W + (size_t)(kt * GBK + br) * U_D + n0 + bc;
        float* b_dst = Bs + buf * GBK * B_LD + br * B_LD + bc;
#pragma unroll
        for (int i = 0; i < 4; i++) cp_async16(b_dst + i * 8 * B_LD, b_src + (size_t)i * 8 * U_D);
    };

    // prologue
    ldregA(0);
    issueB(0, 0);
    cp_commit();
    stsA(0);        // one exposed LDG->STS (tile 0 only)
    ldregA(1);

    for (int kt = 0; kt < NK; ++kt) {
        cp_wait<0>();
        __syncthreads();   // A(kt) STS + B(kt) cp.async visible; prior compute done

        if (kt + 1 < NK) {
            issueB((kt + 1) & 1, kt + 1);   // safe: buffer's readers passed barrier
            cp_commit();
            stsA((kt + 1) & 1);             // regs loaded a full iteration ago
        }
        if (kt + 2 < NK) ldregA(kt + 2);

        const uint32_t sAb = sA + 4u * (uint32_t)((kt & 1) * GBM * A_LD);
        const float* Bb = Bs + (kt & 1) * GBK * B_LD;

#pragma unroll
        for (int kk = 0; kk < 4; kk++) {
            uint32_t a[2][4];
            ldsm4(a[0][0], a[0][1], a[0][2], a[0][3],
                  sAb + 4u * (uint32_t)(wm * A_LD + kk * 8 + aoff));
            ldsm4(a[1][0], a[1][1], a[1][2], a[1][3],
                  sAb + 4u * (uint32_t)((wm + 16) * A_LD + kk * 8 + aoff));
#pragma unroll
            for (int nf = 0; nf < 8; nf++) {
                uint32_t b[2];
                b[0] = __float_as_uint(Bb[(kk * 8 + tg) * B_LD + wn + nf * 8 + g]);
                b[1] = __float_as_uint(Bb[(kk * 8 + tg + 4) * B_LD + wn + nf * 8 + g]);
                mma_tf32(acc[0][nf], a[0], b);
                mma_tf32(acc[1][nf], a[1], b);
            }
        }
    }

    // epilogue: tf32-round (fold scale for Q) so attn consumes gmem directly
#pragma unroll
    for (int mf = 0; mf < 2; mf++) {
        const int r0 = m0 + wm + mf * 16 + g;
#pragma unroll
        for (int nf = 0; nf < 8; nf++) {
            const int c = n0 + wn + nf * 8 + 2 * tg;
            *(float2*)(C + (size_t)r0 * U_D + c) =
                make_float2(f2tf32f(acc[mf][nf][0] * oscale), f2tf32f(acc[mf][nf][1] * oscale));
            *(float2*)(C + (size_t)(r0 + 8) * U_D + c) =
                make_float2(f2tf32f(acc[mf][nf][2] * oscale), f2tf32f(acc[mf][nf][3] * oscale));
        }
    }
}

// ---------------------------------------------------------------------------
// Flash attention (R11 best config; only change: mask LDG issued BEFORE the
// K/V copy inside the load phase so its latency overlaps the 16 LDG/STS
// pairs instead of being exposed at the phase tail).
// KT=64, synchronous K/V float4 copies (gmem pre-rounded tf32, no cvt),
// Q/K/P fragments via ldmatrix, V scalar conflict-free (VL=72), 2 barriers
// per tile. CTA = 128 q-rows x 4 warps; warp owns 32 rows (2 m-frags).
// ---------------------------------------------------------------------------
#define QT 128
#define KT 64
#define AL 68     // LD for Qs/Ks/Ps
#define VL 72     // LD for Vs (8*tg+g hits all 32 banks)
#define SM_ATTN ((QT * AL + KT * AL + KT * VL + QT * AL + KT) * 4)

__global__ void __launch_bounds__(128) attn_kernel(const int* __restrict__ mask,
                                                   float* __restrict__ out) {
    extern __shared__ float sm[];
    float* Qs = sm;                       // [128][AL] tf32, scale folded
    float* Ks = Qs + QT * AL;             // [64][AL]  tf32
    float* Vs = Ks + KT * AL;             // [64][VL]  tf32
    float* Ps = Vs + KT * VL;             // [128][AL] tf32
    float* Msk = Ps + QT * AL;            // [64] 1.0 = masked-out

    const int tid = threadIdx.x, lane = tid & 31, wid = tid >> 5;
    const int g = lane >> 2, tg = lane & 3;
    const int q0 = blockIdx.x * QT;
    const int h = blockIdx.y, n = blockIdx.z;
    const int wrow = wid * 32;

    const uint32_t sQ = (uint32_t)__cvta_generic_to_shared(Qs);
    const uint32_t sK = (uint32_t)__cvta_generic_to_shared(Ks);
    const uint32_t sP = (uint32_t)__cvta_generic_to_shared(Ps);

    // ldmatrix per-lane offsets (floats)
    const int li = lane & 7, lj = lane >> 3;
    const int aoff = (li + (lj & 1) * 8) * AL + (lj >> 1) * 4;  // 16x8 A-frag
    const int boff = (li + (lj >> 1) * 8) * AL + (lj & 1) * 4;  // 2x(8k x 8c) B

    const int lr = tid >> 4;   // 0..7
    const int fc = tid & 15;   // float4 column

    // ---- Q prologue: straight copy (already tf32-rounded + scaled) ----
#pragma unroll
    for (int i = 0; i < 16; i++) {
        const int r = lr + i * 8;
        *(float4*)(Qs + r * AL + fc * 4) =
            *(const float4*)(g_Q + (size_t)(n * T_S + q0 + r) * U_D + h * D_H + fc * 4);
    }

    float mr[2][2], lsum[2][2];
#pragma unroll
    for (int mf = 0; mf < 2; mf++) { mr[mf][0] = mr[mf][1] = -1e30f; lsum[mf][0] = lsum[mf][1] = 0.f; }
    float of[2][8][4];
#pragma unroll
    for (int mf = 0; mf < 2; mf++)
#pragma unroll
        for (int nf = 0; nf < 8; nf++)
#pragma unroll
            for (int i = 0; i < 4; i++) of[mf][nf][i] = 0.f;

    for (int kt = 0; kt < 16; kt++) {
        __syncthreads();  // prior-tile consumers done (and Q store on kt=0)
        const int j0 = kt * KT;
        // mask LDG first: dependent load's latency overlaps the K/V copies
        int mword = 0;
        if (tid < KT) mword = mask[n * T_S + j0 + tid];
#pragma unroll
        for (int i = 0; i < 8; i++) {
            const int r = lr + i * 8;
            const size_t gb = (size_t)(n * T_S + j0 + r) * U_D + h * D_H + fc * 4;
            *(float4*)(Ks + r * AL + fc * 4) = *(const float4*)(g_K + gb);
            *(float4*)(Vs + r * VL + fc * 4) = *(const float4*)(g_V + gb);
        }
        if (tid < KT) Msk[tid] = (mword != 0) ? 0.f : 1.f;
        __syncthreads();

        // ---- S = Q @ K^T ----
        float sf[2][8][4];
#pragma unroll
        for (int mf = 0; mf < 2; mf++)
#pragma unroll
            for (int nf = 0; nf < 8; nf++)
#pragma unroll
                for (int i = 0; i < 4; i++) sf[mf][nf][i] = 0.f;

#pragma unroll
        for (int kk = 0; kk < 8; kk++) {
            uint32_t qa[2][4];
            ldsm4(qa[0][0], qa[0][1], qa[0][2], qa[0][3],
                  sQ + 4u * (uint32_t)(wrow * AL + kk * 8 + aoff));
            ldsm4(qa[1][0], qa[1][1], qa[1][2], qa[1][3],
                  sQ + 4u * (uint32_t)((wrow + 16) * AL + kk * 8 + aoff));
#pragma unroll
            for (int nfp = 0; nfp < 4; nfp++) {
                uint32_t kb[4];
                ldsm4(kb[0], kb[1], kb[2], kb[3],
                      sK + 4u * (uint32_t)(nfp * 16 * AL + kk * 8 + boff));
                mma_tf32(sf[0][2 * nfp], qa[0], kb);
                mma_tf32(sf[1][2 * nfp], qa[1], kb);
                mma_tf32(sf[0][2 * nfp + 1], qa[0], kb + 2);
                mma_tf32(sf[1][2 * nfp + 1], qa[1], kb + 2);
            }
        }

        // ---- mask (jnp.where(mask, s, -1e6)) ----
#pragma unroll
        for (int nf = 0; nf < 8; nf++) {
            const float f0 = Msk[nf * 8 + 2 * tg];
            const float f1 = Msk[nf * 8 + 2 * tg + 1];
#pragma unroll
            for (int mf = 0; mf < 2; mf++) {
                if (f0 != 0.f) { sf[mf][nf][0] = -1e6f; sf[mf][nf][2] = -1e6f; }
                if (f1 != 0.f) { sf[mf][nf][1] = -1e6f; sf[mf][nf][3] = -1e6f; }
            }
        }

        // ---- online softmax + P store ----
#pragma unroll
        for (int mf = 0; mf < 2; mf++) {
            float rm0 = -1e30f, rm1 = -1e30f;
#pragma unroll
            for (int nf = 0; nf < 8; nf++) {
                rm0 = fmaxf(rm0, fmaxf(sf[mf][nf][0], sf[mf][nf][1]));
                rm1 = fmaxf(rm1, fmaxf(sf[mf][nf][2], sf[mf][nf][3]));
            }
            rm0 = fmaxf(rm0, __shfl_xor_sync(0xffffffffu, rm0, 1));
            rm0 = fmaxf(rm0, __shfl_xor_sync(0xffffffffu, rm0, 2));
            rm1 = fmaxf(rm1, __shfl_xor_sync(0xffffffffu, rm1, 1));
            rm1 = fmaxf(rm1, __shfl_xor_sync(0xffffffffu, rm1, 2));

            const float mn0 = fmaxf(mr[mf][0], rm0), mn1 = fmaxf(mr[mf][1], rm1);
            const float al0 = __expf(mr[mf][0] - mn0), al1 = __expf(mr[mf][1] - mn1);
            float rs0 = 0.f, rs1 = 0.f;
#pragma unroll
            for (int nf = 0; nf < 8; nf++) {
                sf[mf][nf][0] = __expf(sf[mf][nf][0] - mn0);
                sf[mf][nf][1] = __expf(sf[mf][nf][1] - mn0);
                sf[mf][nf][2] = __expf(sf[mf][nf][2] - mn1);
                sf[mf][nf][3] = __expf(sf[mf][nf][3] - mn1);
                rs0 += sf[mf][nf][0] + sf[mf][nf][1];
                rs1 += sf[mf][nf][2] + sf[mf][nf][3];
            }
            rs0 += __shfl_xor_sync(0xffffffffu, rs0, 1);
            rs0 += __shfl_xor_sync(0xffffffffu, rs0, 2);
            rs1 += __shfl_xor_sync(0xffffffffu, rs1, 1);
            rs1 += __shfl_xor_sync(0xffffffffu, rs1, 2);

            lsum[mf][0] = lsum[mf][0] * al0 + rs0;
            lsum[mf][1] = lsum[mf][1] * al1 + rs1;
            mr[mf][0] = mn0;
            mr[mf][1] = mn1;

#pragma unroll
            for (int nf = 0; nf < 8; nf++) {
                of[mf][nf][0] *= al0;
                of[mf][nf][1] *= al0;
                of[mf][nf][2] *= al1;
                of[mf][nf][3] *= al1;
            }

            const int pr = wrow + mf * 16;
#pragma unroll
            for (int nf = 0; nf < 8; nf++) {
                *(float2*)(Ps + (pr + g) * AL + nf * 8 + 2 * tg) =
                    make_float2(f2tf32f(sf[mf][nf][0]), f2tf32f(sf[mf][nf][1]));
                *(float2*)(Ps + (pr + g + 8) * AL + nf * 8 + 2 * tg) =
                    make_float2(f2tf32f(sf[mf][nf][2]), f2tf32f(sf[mf][nf][3]));
            }
        }
        __syncwarp();

        // ---- O += P @ V ----
#pragma unroll
        for (int kks = 0; kks < 8; kks++) {
            uint32_t pa[2][4];
            ldsm4(pa[0][0], pa[0][1], pa[0][2], pa[0][3],
                  sP + 4u * (uint32_t)(wrow * AL + kks * 8 + aoff));
            ldsm4(pa[1][0], pa[1][1], pa[1][2], pa[1][3],
                  sP + 4u * (uint32_t)((wrow + 16) * AL + kks * 8 + aoff));
#pragma unroll
            for (int nf = 0; nf < 8; nf++) {
                uint32_t vb[2];
                vb[0] = __float_as_uint(Vs[(kks * 8 + tg) * VL + nf * 8 + g]);
                vb[1] = __float_as_uint(Vs[(kks * 8 + tg + 4) * VL + nf * 8 + g]);
                mma_tf32(of[0][nf], pa[0], vb);
                mma_tf32(of[1][nf], pa[1], vb);
            }
        }
    }

    // ---- epilogue ----
#pragma unroll
    for (int mf = 0; mf < 2; mf++) {
        const float il0 = 1.f / lsum[mf][0], il1 = 1.f / lsum[mf][1];
        const int r0 = q0 + wrow + mf * 16 + g;
#pragma unroll
        for (int nf = 0; nf < 8; nf++) {
            const int c = h * D_H + nf * 8 + 2 * tg;
            *(float2*)(out + (size_t)(n * T_S + r0) * U_D + c) =
                make_float2(of[mf][nf][0] * il0, of[mf][nf][1] * il0);
            *(float2*)(out + (size_t)(n * T_S + r0 + 8) * U_D + c) =
                make_float2(of[mf][nf][2] * il1, of[mf][nf][3] * il1);
        }
    }
}

// ---------------------------------------------------------------------------
// Launch
// ---------------------------------------------------------------------------
extern "C" void kernel_launch(void* const* d_in, const int* in_sizes, int n_in,
                              void* d_out, int out_size) {
    const float* q = (const float*)d_in[0];
    const float* k = (const float*)d_in[1];
    const int* mask = (const int*)d_in[2];
    const float* Wq = (const float*)d_in[3];
    const float* Wk = (const float*)d_in[4];
    const float* Wv = (const float*)d_in[5];
    float* out = (float*)d_out;

    cudaFuncSetAttribute(proj_gemm, cudaFuncAttributeMaxDynamicSharedMemorySize, SM_GEMM);
    cudaFuncSetAttribute(attn_kernel, cudaFuncAttributeMaxDynamicSharedMemorySize, SM_ATTN);

    // Pre-round the weights (3 MB) to tf32; 2 float4 per thread (MLP=2)
    preround_w<<<dim3(D_IN * U_D / 4 / 512, 3), 256>>>(Wq, Wk, Wv);

    // Projections: 64 x 4 x 3 = 768 CTAs of 256 threads (hybrid pipeline)
    proj_gemm<<<dim3((N_B * T_S) / GBM, U_D / GBN, 3), 256, SM_GEMM>>>(q, k);

    // q-tiles x-fastest: 8 CTAs per (h,n) share the K/V slice in L2
    attn_kernel<<<dim3(T_S / QT, H_N, N_B), 128, SM_ATTN>>>(mask, out);
}

// round 16
// speedup vs baseline: 1.0183x; 1.0183x over previous
#include <cuda_runtime.h>
#include <cstdint>

#define N_B 8
#define T_S 1024
#define D_IN 512
#define U_D 512
#define H_N 8
#define D_H 64

// Scratch: projected Q/K/V (tf32-rounded; Q pre-scaled) + tf32-rounded W.
__device__ float g_Q[N_B * T_S * U_D];
__device__ float g_K[N_B * T_S * U_D];
__device__ float g_V[N_B * T_S * U_D];
__device__ float g_W[3 * D_IN * U_D];      // tf32(Wq|Wk|Wv), k-major

// ---------------------------------------------------------------------------
// Helpers
// ---------------------------------------------------------------------------
__device__ __forceinline__ uint32_t f2tf32(float x) {
    uint32_t r;
    asm("cvt.rna.tf32.f32 %0, %1;" : "=r"(r) : "f"(x));
    return r;
}
__device__ __forceinline__ float f2tf32f(float x) { return __uint_as_float(f2tf32(x)); }

// D += A*B, m16n8k8 tf32. a[4], b[2] are tf32 bit patterns.
__device__ __forceinline__ void mma_tf32(float* d, const uint32_t* a, const uint32_t* b) {
    asm volatile(
        "mma.sync.aligned.m16n8k8.row.col.f32.tf32.tf32.f32 "
        "{%0,%1,%2,%3},{%4,%5,%6,%7},{%8,%9},{%0,%1,%2,%3};\n"
        : "+f"(d[0]), "+f"(d[1]), "+f"(d[2]), "+f"(d[3])
        : "r"(a[0]), "r"(a[1]), "r"(a[2]), "r"(a[3]), "r"(b[0]), "r"(b[1]));
}

__device__ __forceinline__ void ldsm4(uint32_t& r0, uint32_t& r1, uint32_t& r2, uint32_t& r3,
                                      uint32_t addr) {
    asm volatile("ldmatrix.sync.aligned.m8n8.x4.shared.b16 {%0,%1,%2,%3}, [%4];"
                 : "=r"(r0), "=r"(r1), "=r"(r2), "=r"(r3)
                 : "r"(addr));
}

__device__ __forceinline__ void cp_async16(float* s, const float* g) {
    uint32_t sa = (uint32_t)__cvta_generic_to_shared(s);
    asm volatile("cp.async.cg.shared.global [%0], [%1], 16;\n" :: "r"(sa), "l"(g));
}
__device__ __forceinline__ void cp_commit() { asm volatile("cp.async.commit_group;\n"); }
template <int N>
__device__ __forceinline__ void cp_wait() { asm volatile("cp.async.wait_group %0;\n" :: "n"(N)); }

// ---------------------------------------------------------------------------
// Pre-round W only: 3 MB of pre-round traffic (R11 exact version).
// ---------------------------------------------------------------------------
__global__ void __launch_bounds__(256) preround_w(
    const float* __restrict__ wq, const float* __restrict__ wk,
    const float* __restrict__ wv) {
    const int i = blockIdx.x * 256 + threadIdx.x;  // float4 index
    const int NW4 = D_IN * U_D / 4;                // 65536
    if (i < NW4) {
        float4 a = ((const float4*)wq)[i];
        a.x = f2tf32f(a.x); a.y = f2tf32f(a.y); a.z = f2tf32f(a.z); a.w = f2tf32f(a.w);
        ((float4*)g_W)[i] = a;
        float4 b = ((const float4*)wk)[i];
        b.x = f2tf32f(b.x); b.y = f2tf32f(b.y); b.z = f2tf32f(b.z); b.w = f2tf32f(b.w);
        ((float4*)g_W)[NW4 + i] = b;
        float4 c = ((const float4*)wv)[i];
        c.x = f2tf32f(c.x); c.y = f2tf32f(c.y); c.z = f2tf32f(c.z); c.w = f2tf32f(c.w);
        ((float4*)g_W)[2 * NW4 + i] = c;
    }
}

// ---------------------------------------------------------------------------
// Projection GEMM (R11 measured winner, byte-identical):
// C[8192,512] = X[8192,512] @ W[512,512]
// B (pre-rounded W, k-major) via cp.async double-buffer, scalar conflict-free
// B-frags (B_LD=136 -> 8*tg+g banks); A (raw X) via register prefetch +
// cvt-at-STS into double buffer (off critical path).
// BM=128, BN=128, BK=32; 256 threads; warp tile 32x64 (ldsm A).
// Epilogue rounds output to tf32 (Q folded with 1/sqrt(512)).
// ---------------------------------------------------------------------------
#define GBM 128
#define GBN 128
#define GBK 32
#define A_LD 36
#define B_LD 136
#define SM_GEMM ((2 * GBM * A_LD + 2 * GBK * B_LD) * 4)

__global__ void __launch_bounds__(256, 2) proj_gemm(
    const float* __restrict__ Xq, const float* __restrict__ Xk) {
    const float* X;
    const float* W;
    float* C;
    float oscale;
    if (blockIdx.z == 0) { X = Xq; W = g_W; C = g_Q; oscale = 0.04419417382415922f; }
    else if (blockIdx.z == 1) { X = Xk; W = g_W + D_IN * U_D; C = g_K; oscale = 1.0f; }
    else { X = Xk; W = g_W + 2 * D_IN * U_D; C = g_V; oscale = 1.0f; }

    extern __shared__ float sm[];
    float* As = sm;                            // [2][GBM][A_LD]
    float* Bs = sm + 2 * GBM * A_LD;           // [2][GBK][B_LD]

    const int tid = threadIdx.x;
    const int m0 = blockIdx.x * GBM, n0 = blockIdx.y * GBN;
    const int ar = tid >> 3, ac = (tid & 7) * 4;     // A: 32 rows/step, 8 f4/row
    const int br = tid >> 5, bc = (tid & 31) * 4;    // B: 8 rows/step, 32 f4/row

    const int lane = tid & 31, wid = tid >> 5;
    const int g = lane >> 2, tg = lane & 3;
    const int wm = (wid & 3) * 32, wn = (wid >> 2) * 64;

    // ldmatrix A-frag per-lane offset (16x8 pattern, floats)
    const int li = lane & 7, lj = lane >> 3;
    const int aoff = (li + (lj & 1) * 8) * A_LD + (lj >> 1) * 4;
    const uint32_t sA = (uint32_t)__cvta_generic_to_shared(As);

    float acc[2][8][4];
#pragma unroll
    for (int mf = 0; mf < 2; mf++)
#pragma unroll
        for (int nf = 0; nf < 8; nf++)
#pragma unroll
            for (int i = 0; i < 4; i++) acc[mf][nf][i] = 0.f;

    const int NK = D_IN / GBK;  // 16

    float4 pa[4];
    auto ldregA = [&](int kt) {
#pragma unroll
        for (int i = 0; i < 4; i++)
            pa[i] = *(const float4*)(X + (size_t)(m0 + ar + i * 32) * D_IN + kt * GBK + ac);
    };
    auto stsA = [&](int buf) {
#pragma unroll
        for (int i = 0; i < 4; i++) {
            float4 o;
            o.x = f2tf32f(pa[i].x); o.y = f2tf32f(pa[i].y);
            o.z = f2tf32f(pa[i].z); o.w = f2tf32f(pa[i].w);
            *(float4*)(As + buf * GBM * A_LD + (ar + i * 32) * A_LD + ac) = o;
        }
    };
    auto issueB = [&](int buf, int kt) {
        const float* b_src = W + (size_t)(kt * GBK + br) * U_D + n0 + bc;
        float* b_dst = Bs + buf * GBK * B_LD + br * B_LD + bc;
#pragma unroll
        for (int i = 0; i < 4; i++) cp_async16(b_dst + i * 8 * B_LD, b_src + (size_t)i * 8 * U_D);
    };

    // prologue
    ldregA(0);
    issueB(0, 0);
    cp_commit();
    stsA(0);        // one exposed LDG->STS (tile 0 only)
    ldregA(1);

    for (int kt = 0; kt < NK; ++kt) {
        cp_wait<0>();
        __syncthreads();   // A(kt) STS + B(kt) cp.async visible; prior compute done

        if (kt + 1 < NK) {
            issueB((kt + 1) & 1, kt + 1);   // safe: buffer's readers passed barrier
            cp_commit();
            stsA((kt + 1) & 1);             // regs loaded a full iteration ago
        }
        if (kt + 2 < NK) ldregA(kt + 2);

        const uint32_t sAb = sA + 4u * (uint32_t)((kt & 1) * GBM * A_LD);
        const float* Bb = Bs + (kt & 1) * GBK * B_LD;

#pragma unroll
        for (int kk = 0; kk < 4; kk++) {
            uint32_t a[2][4];
            ldsm4(a[0][0], a[0][1], a[0][2], a[0][3],
                  sAb + 4u * (uint32_t)(wm * A_LD + kk * 8 + aoff));
            ldsm4(a[1][0], a[1][1], a[1][2], a[1][3],
                  sAb + 4u * (uint32_t)((wm + 16) * A_LD + kk * 8 + aoff));
#pragma unroll
            for (int nf = 0; nf < 8; nf++) {
                uint32_t b[2];
                b[0] = __float_as_uint(Bb[(kk * 8 + tg) * B_LD + wn + nf * 8 + g]);
                b[1] = __float_as_uint(Bb[(kk * 8 + tg + 4) * B_LD + wn + nf * 8 + g]);
                mma_tf32(acc[0][nf], a[0], b);
                mma_tf32(acc[1][nf], a[1], b);
            }
        }
    }

    // epilogue: tf32-round (fold scale for Q) so attn consumes gmem directly
#pragma unroll
    for (int mf = 0; mf < 2; mf++) {
        const int r0 = m0 + wm + mf * 16 + g;
#pragma unroll
        for (int nf = 0; nf < 8; nf++) {
            const int c = n0 + wn + nf * 8 + 2 * tg;
            *(float2*)(C + (size_t)r0 * U_D + c) =
                make_float2(f2tf32f(acc[mf][nf][0] * oscale), f2tf32f(acc[mf][nf][1] * oscale));
            *(float2*)(C + (size_t)(r0 + 8) * U_D + c) =
                make_float2(f2tf32f(acc[mf][nf][2] * oscale), f2tf32f(acc[mf][nf][3] * oscale));
        }
    }
}

// ---------------------------------------------------------------------------
// Flash attention (R11 measured winner, byte-identical):
// KT=64, synchronous K/V float4 copies (gmem pre-rounded tf32, no cvt),
// Q/K/P fragments via ldmatrix, V scalar conflict-free (VL=72), 2 barriers
// per tile. CTA = 128 q-rows x 4 warps; warp owns 32 rows (2 m-frags).
// ---------------------------------------------------------------------------
#define QT 128
#define KT 64
#define AL 68     // LD for Qs/Ks/Ps
#define VL 72     // LD for Vs (8*tg+g hits all 32 banks)
#define SM_ATTN ((QT * AL + KT * AL + KT * VL + QT * AL + KT) * 4)

__global__ void __launch_bounds__(128) attn_kernel(const int* __restrict__ mask,
                                                   float* __restrict__ out) {
    extern __shared__ float sm[];
    float* Qs = sm;                       // [128][AL] tf32, scale folded
    float* Ks = Qs + QT * AL;             // [64][AL]  tf32
    float* Vs = Ks + KT * AL;             // [64][VL]  tf32
    float* Ps = Vs + KT * VL;             // [128][AL] tf32
    float* Msk = Ps + QT * AL;            // [64] 1.0 = masked-out

    const int tid = threadIdx.x, lane = tid & 31, wid = tid >> 5;
    const int g = lane >> 2, tg = lane & 3;
    const int q0 = blockIdx.x * QT;
    const int h = blockIdx.y, n = blockIdx.z;
    const int wrow = wid * 32;

    const uint32_t sQ = (uint32_t)__cvta_generic_to_shared(Qs);
    const uint32_t sK = (uint32_t)__cvta_generic_to_shared(Ks);
    const uint32_t sP = (uint32_t)__cvta_generic_to_shared(Ps);

    // ldmatrix per-lane offsets (floats)
    const int li = lane & 7, lj = lane >> 3;
    const int aoff = (li + (lj & 1) * 8) * AL + (lj >> 1) * 4;  // 16x8 A-frag
    const int boff = (li + (lj >> 1) * 8) * AL + (lj & 1) * 4;  // 2x(8k x 8c) B

    const int lr = tid >> 4;   // 0..7
    const int fc = tid & 15;   // float4 column

    // ---- Q prologue: straight copy (already tf32-rounded + scaled) ----
#pragma unroll
    for (int i = 0; i < 16; i++) {
        const int r = lr + i * 8;
        *(float4*)(Qs + r * AL + fc * 4) =
            *(const float4*)(g_Q + (size_t)(n * T_S + q0 + r) * U_D + h * D_H + fc * 4);
    }

    float mr[2][2], lsum[2][2];
#pragma unroll
    for (int mf = 0; mf < 2; mf++) { mr[mf][0] = mr[mf][1] = -1e30f; lsum[mf][0] = lsum[mf][1] = 0.f; }
    float of[2][8][4];
#pragma unroll
    for (int mf = 0; mf < 2; mf++)
#pragma unroll
        for (int nf = 0; nf < 8; nf++)
#pragma unroll
            for (int i = 0; i < 4; i++) of[mf][nf][i] = 0.f;

    for (int kt = 0; kt < 16; kt++) {
        __syncthreads();  // prior-tile consumers done (and Q store on kt=0)
        const int j0 = kt * KT;
#pragma unroll
        for (int i = 0; i < 8; i++) {
            const int r = lr + i * 8;
            const size_t gb = (size_t)(n * T_S + j0 + r) * U_D + h * D_H + fc * 4;
            *(float4*)(Ks + r * AL + fc * 4) = *(const float4*)(g_K + gb);
            *(float4*)(Vs + r * VL + fc * 4) = *(const float4*)(g_V + gb);
        }
        if (tid < KT) Msk[tid] = (mask[n * T_S + j0 + tid] != 0) ? 0.f : 1.f;
        __syncthreads();

        // ---- S = Q @ K^T ----
        float sf[2][8][4];
#pragma unroll
        for (int mf = 0; mf < 2; mf++)
#pragma unroll
            for (int nf = 0; nf < 8; nf++)
#pragma unroll
                for (int i = 0; i < 4; i++) sf[mf][nf][i] = 0.f;

#pragma unroll
        for (int kk = 0; kk < 8; kk++) {
            uint32_t qa[2][4];
            ldsm4(qa[0][0], qa[0][1], qa[0][2], qa[0][3],
                  sQ + 4u * (uint32_t)(wrow * AL + kk * 8 + aoff));
            ldsm4(qa[1][0], qa[1][1], qa[1][2], qa[1][3],
                  sQ + 4u * (uint32_t)((wrow + 16) * AL + kk * 8 + aoff));
#pragma unroll
            for (int nfp = 0; nfp < 4; nfp++) {
                uint32_t kb[4];
                ldsm4(kb[0], kb[1], kb[2], kb[3],
                      sK + 4u * (uint32_t)(nfp * 16 * AL + kk * 8 + boff));
                mma_tf32(sf[0][2 * nfp], qa[0], kb);
                mma_tf32(sf[1][2 * nfp], qa[1], kb);
                mma_tf32(sf[0][2 * nfp + 1], qa[0], kb + 2);
                mma_tf32(sf[1][2 * nfp + 1], qa[1], kb + 2);
            }
        }

        // ---- mask (jnp.where(mask, s, -1e6)) ----
#pragma unroll
        for (int nf = 0; nf < 8; nf++) {
            const float f0 = Msk[nf * 8 + 2 * tg];
            const float f1 = Msk[nf * 8 + 2 * tg + 1];
#pragma unroll
            for (int mf = 0; mf < 2; mf++) {
                if (f0 != 0.f) { sf[mf][nf][0] = -1e6f; sf[mf][nf][2] = -1e6f; }
                if (f1 != 0.f) { sf[mf][nf][1] = -1e6f; sf[mf][nf][3] = -1e6f; }
            }
        }

        // ---- online softmax + P store ----
#pragma unroll
        for (int mf = 0; mf < 2; mf++) {
            float rm0 = -1e30f, rm1 = -1e30f;
#pragma unroll
            for (int nf = 0; nf < 8; nf++) {
                rm0 = fmaxf(rm0, fmaxf(sf[mf][nf][0], sf[mf][nf][1]));
                rm1 = fmaxf(rm1, fmaxf(sf[mf][nf][2], sf[mf][nf][3]));
            }
            rm0 = fmaxf(rm0, __shfl_xor_sync(0xffffffffu, rm0, 1));
            rm0 = fmaxf(rm0, __shfl_xor_sync(0xffffffffu, rm0, 2));
            rm1 = fmaxf(rm1, __shfl_xor_sync(0xffffffffu, rm1, 1));
            rm1 = fmaxf(rm1, __shfl_xor_sync(0xffffffffu, rm1, 2));

            const float mn0 = fmaxf(mr[mf][0], rm0), mn1 = fmaxf(mr[mf][1], rm1);
            const float al0 = __expf(mr[mf][0] - mn0), al1 = __expf(mr[mf][1] - mn1);
            float rs0 = 0.f, rs1 = 0.f;
#pragma unroll
            for (int nf = 0; nf < 8; nf++) {
                sf[mf][nf][0] = __expf(sf[mf][nf][0] - mn0);
                sf[mf][nf][1] = __expf(sf[mf][nf][1] - mn0);
                sf[mf][nf][2] = __expf(sf[mf][nf][2] - mn1);
                sf[mf][nf][3] = __expf(sf[mf][nf][3] - mn1);
                rs0 += sf[mf][nf][0] + sf[mf][nf][1];
                rs1 += sf[mf][nf][2] + sf[mf][nf][3];
            }
            rs0 += __shfl_xor_sync(0xffffffffu, rs0, 1);
            rs0 += __shfl_xor_sync(0xffffffffu, rs0, 2);
            rs1 += __shfl_xor_sync(0xffffffffu, rs1, 1);
            rs1 += __shfl_xor_sync(0xffffffffu, rs1, 2);

            lsum[mf][0] = lsum[mf][0] * al0 + rs0;
            lsum[mf][1] = lsum[mf][1] * al1 + rs1;
            mr[mf][0] = mn0;
            mr[mf][1] = mn1;

#pragma unroll
            for (int nf = 0; nf < 8; nf++) {
                of[mf][nf][0] *= al0;
                of[mf][nf][1] *= al0;
                of[mf][nf][2] *= al1;
                of[mf][nf][3] *= al1;
            }

            const int pr = wrow + mf * 16;
#pragma unroll
            for (int nf = 0; nf < 8; nf++) {
                *(float2*)(Ps + (pr + g) * AL + nf * 8 + 2 * tg) =
                    make_float2(f2tf32f(sf[mf][nf][0]), f2tf32f(sf[mf][nf][1]));
                *(float2*)(Ps + (pr + g + 8) * AL + nf * 8 + 2 * tg) =
                    make_float2(f2tf32f(sf[mf][nf][2]), f2tf32f(sf[mf][nf][3]));
            }
        }
        __syncwarp();

        // ---- O += P @ V ----
#pragma unroll
        for (int kks = 0; kks < 8; kks++) {
            uint32_t pa[2][4];
            ldsm4(pa[0][0], pa[0][1], pa[0][2], pa[0][3],
                  sP + 4u * (uint32_t)(wrow * AL + kks * 8 + aoff));
            ldsm4(pa[1][0], pa[1][1], pa[1][2], pa[1][3],
                  sP + 4u * (uint32_t)((wrow + 16) * AL + kks * 8 + aoff));
#pragma unroll
            for (int nf = 0; nf < 8; nf++) {
                uint32_t vb[2];
                vb[0] = __float_as_uint(Vs[(kks * 8 + tg) * VL + nf * 8 + g]);
                vb[1] = __float_as_uint(Vs[(kks * 8 + tg + 4) * VL + nf * 8 + g]);
                mma_tf32(of[0][nf], pa[0], vb);
                mma_tf32(of[1][nf], pa[1], vb);
            }
        }
    }

    // ---- epilogue ----
#pragma unroll
    for (int mf = 0; mf < 2; mf++) {
        const float il0 = 1.f / lsum[mf][0], il1 = 1.f / lsum[mf][1];
        const int r0 = q0 + wrow + mf * 16 + g;
#pragma unroll
        for (int nf = 0; nf < 8; nf++) {
            const int c = h * D_H + nf * 8 + 2 * tg;
            *(float2*)(out + (size_t)(n * T_S + r0) * U_D + c) =
                make_float2(of[mf][nf][0] * il0, of[mf][nf][1] * il0);
            *(float2*)(out + (size_t)(n * T_S + r0 + 8) * U_D + c) =
                make_float2(of[mf][nf][2] * il1, of[mf][nf][3] * il1);
        }
    }
}

// ---------------------------------------------------------------------------
// Launch
// ---------------------------------------------------------------------------
extern "C" void kernel_launch(void* const* d_in, const int* in_sizes, int n_in,
                              void* d_out, int out_size) {
    const float* q = (const float*)d_in[0];
    const float* k = (const float*)d_in[1];
    const int* mask = (const int*)d_in[2];
    const float* Wq = (const float*)d_in[3];
    const float* Wk = (const float*)d_in[4];
    const float* Wv = (const float*)d_in[5];
    float* out = (float*)d_out;

    cudaFuncSetAttribute(proj_gemm, cudaFuncAttributeMaxDynamicSharedMemorySize, SM_GEMM);
    cudaFuncSetAttribute(attn_kernel, cudaFuncAttributeMaxDynamicSharedMemorySize, SM_ATTN);

    // Pre-round only the weights (3 MB) to tf32
    preround_w<<<(D_IN * U_D / 4 + 255) / 256, 256>>>(Wq, Wk, Wv);

    // Projections: 64 x 4 x 3 = 768 CTAs of 256 threads (hybrid pipeline)
    proj_gemm<<<dim3((N_B * T_S) / GBM, U_D / GBN, 3), 256, SM_GEMM>>>(q, k);

    // q-tiles x-fastest: 8 CTAs per (h,n) share the K/V slice in L2
    attn_kernel<<<dim3(T_S / QT, H_N, N_B), 128, SM_ATTN>>>(mask, out);
}